// round 10
// baseline (speedup 1.0000x reference)
#include <cuda_runtime.h>

#define B_ 32
#define N_ 524288          // 2^19 points per batch
#define K_ 16384
#define T_RANK 425984u     // 3.25 * 2^17; E[cand] ~ 18.6k, 17 sigma above K
#define CAP 32768          // per-batch candidate capacity (15-bit slot)
#define FBINS 8192         // bins: bin = rank>>6 (only bins < 6656 used)
#define EX_CAP 64          // boundary-bin extras capacity (bin ~ Poisson(2.8))
#define SCAT_BPB 16        // scatter blocks per batch
#define BG_BPB 26          // bingather blocks per batch (26*256 = 6656 bins)
#define SEG_CAP 1280       // max keys per 256-bin segment (E~716, >20 sigma)

// key layout: [63:34]=rank(23 used)  [33:15]=idx(19)  [14:0]=slot(15)
// sorting by key == sorting by (rank, idx) since idx is unique per batch.

// ---------------- static device scratch (zero-init; kernels restore invariants) ----------------
__device__ int                g_cand_cnt[B_];
__device__ unsigned           g_hist[B_ * FBINS];      // built by k_main, zeroed by k_scan
__device__ unsigned long long g_cand[B_ * CAP];        // unordered candidate keys
__device__ float              g_cx[B_ * CAP];          // candidate coords (SoA, L2-resident)
__device__ float              g_cy[B_ * CAP];
__device__ float              g_cz[B_ * CAP];
__device__ unsigned           g_binstart[B_ * FBINS];  // exclusive bin offsets (static)
__device__ unsigned           g_off[B_ * FBINS];       // working copy for scatter atomics
__device__ unsigned long long g_dst[B_ * K_];          // binned keys
__device__ unsigned long long g_extras[B_ * EX_CAP];
__device__ int                g_extra_cnt[B_];
__device__ unsigned           g_bstar[B_], g_base[B_], g_need[B_];

struct KeysParam { unsigned k[2 * B_]; };

// ---------------- threefry2x32, 20 rounds (exact JAX partitionable) ----------------
__host__ __device__ __forceinline__ unsigned rotl32(unsigned x, int r) {
#if defined(__CUDA_ARCH__)
    return __funnelshift_l(x, x, r);
#else
    return (x << r) | (x >> (32 - r));
#endif
}

__host__ __device__ __forceinline__ void tf2x32(unsigned k0, unsigned k1,
                                                unsigned x0, unsigned x1,
                                                unsigned& o0, unsigned& o1) {
    unsigned ks2 = k0 ^ k1 ^ 0x1BD11BDAu;
    x0 += k0; x1 += k1;
#define TF_ROUND(r) { x0 += x1; x1 = rotl32(x1, r); x1 ^= x0; }
    TF_ROUND(13) TF_ROUND(15) TF_ROUND(26) TF_ROUND(6)
    x0 += k1;  x1 += ks2 + 1u;
    TF_ROUND(17) TF_ROUND(29) TF_ROUND(16) TF_ROUND(24)
    x0 += ks2; x1 += k0 + 2u;
    TF_ROUND(13) TF_ROUND(15) TF_ROUND(26) TF_ROUND(6)
    x0 += k0;  x1 += k1 + 3u;
    TF_ROUND(17) TF_ROUND(29) TF_ROUND(16) TF_ROUND(24)
    x0 += k1;  x1 += ks2 + 4u;
    TF_ROUND(13) TF_ROUND(15) TF_ROUND(26) TF_ROUND(6)
    x0 += ks2; x1 += k0 + 5u;
#undef TF_ROUND
    o0 = x0; o1 = x1;
}

// ---------------- P1: validity + threefry + collect (keys + coords) + histogram ----------------
__global__ void k_main(const float* __restrict__ p, KeysParam keys) {
    __shared__ int s_woff[8];
    __shared__ int s_base;

    unsigned t  = blockIdx.x * blockDim.x + threadIdx.x;   // one thread = 4 points
    unsigned e0 = t * 4u;
    unsigned b  = e0 >> 19;
    unsigned i0 = e0 & (N_ - 1);

    const float4* pv = reinterpret_cast<const float4*>(p) + (size_t)t * 3;
    float4 v0 = pv[0], v1 = pv[1], v2 = pv[2];
    float c[12] = { v0.x, v0.y, v0.z, v0.w, v1.x, v1.y,
                    v1.z, v1.w, v2.x, v2.y, v2.z, v2.w };

    unsigned k0 = keys.k[2 * b], k1 = keys.k[2 * b + 1];

    unsigned rank[4];
    bool cand[4];
#pragma unroll
    for (int j = 0; j < 4; j++) {
        float s = (c[3 * j] + c[3 * j + 1]) + c[3 * j + 2];   // XLA left-assoc sum
        unsigned a, d;
        tf2x32(k0, k1, 0u, i0 + (unsigned)j, a, d);           // counter (0, i)
        rank[j] = (a ^ d) >> 9;                               // 23-bit rank
        cand[j] = (s != 0.0f) && (rank[j] < T_RANK);
    }

    unsigned lane = threadIdx.x & 31u;
    unsigned wid  = threadIdx.x >> 5;
    unsigned lt_mask = (1u << lane) - 1u;
    unsigned msk[4];
    int tot = 0;
#pragma unroll
    for (int j = 0; j < 4; j++) {
        msk[j] = __ballot_sync(0xFFFFFFFFu, cand[j]);
        tot += __popc(msk[j]);
    }
    if (lane == 0) s_woff[wid] = tot;
    __syncthreads();
    if (threadIdx.x == 0) {
        int sum = 0;
#pragma unroll
        for (int w = 0; w < 8; w++) { int cc = s_woff[w]; s_woff[w] = sum; sum += cc; }
        s_base = atomicAdd(&g_cand_cnt[b], sum);
    }
    __syncthreads();
    int running = s_base + s_woff[wid];
#pragma unroll
    for (int j = 0; j < 4; j++) {
        if (cand[j]) {
            int pos = running + __popc(msk[j] & lt_mask);
            if (pos < CAP) {
                unsigned long long key =
                    ((unsigned long long)rank[j] << 34) |
                    ((unsigned long long)(i0 + j) << 15) |
                    (unsigned long long)pos;
                size_t sl = (size_t)b * CAP + pos;
                g_cand[sl] = key;
                g_cx[sl] = c[3 * j];
                g_cy[sl] = c[3 * j + 1];
                g_cz[sl] = c[3 * j + 2];
            }
            atomicAdd(&g_hist[b * FBINS + (rank[j] >> 6)], 1u);   // RED, no return
        }
        running += __popc(msk[j]);
    }
}

// ---------------- P2: per-batch scan -> bin offsets + exact threshold ----------------
__global__ void k_scan() {
    __shared__ unsigned s_wsum[32];
    __shared__ unsigned offs[FBINS];

    int b = blockIdx.x, t = threadIdx.x;                 // 1024 threads
    unsigned lane = t & 31u, wid = t >> 5;
    unsigned* hist = &g_hist[b * FBINS];

    {
        const uint4* hv = reinterpret_cast<const uint4*>(hist);
        uint4* ov = reinterpret_cast<uint4*>(offs);
        ov[t]        = hv[t];
        ov[t + 1024] = hv[t + 1024];
    }
    __syncthreads();

    unsigned loc[FBINS / 1024], run = 0;
#pragma unroll
    for (int r = 0; r < FBINS / 1024; r++) { loc[r] = run; run += offs[t * (FBINS / 1024) + r]; }
    unsigned wincl = run;
    for (int off = 1; off < 32; off <<= 1) {
        unsigned v = __shfl_up_sync(0xFFFFFFFFu, wincl, off);
        if (lane >= (unsigned)off) wincl += v;
    }
    if (lane == 31u) s_wsum[wid] = wincl;
    __syncthreads();
    if (wid == 0) {
        unsigned v = s_wsum[lane];
        unsigned sc = v;
        for (int off = 1; off < 32; off <<= 1) {
            unsigned u = __shfl_up_sync(0xFFFFFFFFu, sc, off);
            if (lane >= (unsigned)off) sc += u;
        }
        s_wsum[lane] = sc - v;
    }
    __syncthreads();
    unsigned incl = wincl + s_wsum[wid];
    unsigned excl = incl - run;

    if (excl < (unsigned)K_ && incl >= (unsigned)K_) {   // unique crossing thread
        unsigned cum = excl;
#pragma unroll
        for (int r = 0; r < FBINS / 1024; r++) {
            unsigned cc = offs[t * (FBINS / 1024) + r];
            if (cum + cc >= (unsigned)K_) {
                g_bstar[b] = (unsigned)(t * (FBINS / 1024) + r);
                g_base[b]  = cum;
                g_need[b]  = (unsigned)K_ - cum;
                break;
            }
            cum += cc;
        }
    }
#pragma unroll
    for (int r = 0; r < FBINS / 1024; r++) {
        unsigned bin = (unsigned)t * (FBINS / 1024) + r;
        unsigned v = excl + loc[r];
        g_binstart[b * FBINS + bin] = v;
        g_off     [b * FBINS + bin] = v;
    }
    {
        uint4 z = make_uint4(0, 0, 0, 0);
        uint4* hv = reinterpret_cast<uint4*>(hist);
        hv[t] = z; hv[t + 1024] = z;
    }
}

// ---------------- P3: full-chip scatter into bins ----------------
__global__ void k_scatter() {
    int b   = blockIdx.x / SCAT_BPB;
    int sub = blockIdx.x % SCAT_BPB;
    int t   = sub * 256 + threadIdx.x;
    const unsigned long long* cand = &g_cand[(size_t)b * CAP];
    unsigned long long* dst = &g_dst[(size_t)b * K_];
    unsigned bstar = g_bstar[b];
    int C = g_cand_cnt[b]; if (C > CAP) C = CAP;

    for (int i = t; i < C; i += SCAT_BPB * 256) {
        unsigned long long key = cand[i];
        unsigned bin = (unsigned)(key >> 40);            // rank>>6
        if (bin < bstar) {
            unsigned pos = atomicAdd(&g_off[b * FBINS + bin], 1u);
            dst[pos] = key;
        } else if (bin == bstar) {
            int ep = atomicAdd(&g_extra_cnt[b], 1);
            if (ep < EX_CAP) g_extras[b * EX_CAP + ep] = key;
        }
    }
}

// ---------------- P4: segment-staged per-bin sort + L2-resident gather ----------------
__global__ void k_bingather(float* __restrict__ out) {
    __shared__ unsigned long long seg[SEG_CAP];
    __shared__ unsigned long long sx[EX_CAP];

    int blk = blockIdx.x;
    int b   = blk / BG_BPB;
    int g   = blk % BG_BPB;
    int t   = threadIdx.x;                               // 256 threads
    unsigned bin0  = (unsigned)(g * 256);
    unsigned bstar = g_bstar[b];

    float* ob = out + (size_t)b * K_ * 3;
    const unsigned long long* dst = &g_dst[(size_t)b * K_];
    const unsigned* bs = &g_binstart[b * FBINS];
    size_t cbase = (size_t)b * CAP;

    unsigned binEnd = bin0 + 256u; if (binEnd > bstar) binEnd = bstar;
    if (bin0 < bstar) {
        unsigned lo  = bs[bin0];
        unsigned hi  = bs[binEnd];
        unsigned len = hi - lo; if (len > SEG_CAP) len = SEG_CAP;

        for (unsigned i = t; i < len; i += 256) seg[i] = dst[lo + i];
        __syncthreads();

        unsigned bin = bin0 + (unsigned)t;
        if (bin < binEnd) {
            unsigned s = bs[bin] - lo;
            unsigned e = bs[bin + 1] - lo;
            if (e > len) e = len;
            if (s > len) s = len;
            for (unsigned i = s + 1; i < e; i++) {
                unsigned long long v = seg[i];
                unsigned jj = i;
                while (jj > s && seg[jj - 1] > v) { seg[jj] = seg[jj - 1]; jj--; }
                seg[jj] = v;
            }
        }
        __syncthreads();

        // gather from L2-resident candidate coords (slot in key low bits)
        for (unsigned i = t; i < len; i += 256) {
            unsigned slot = (unsigned)(seg[i] & 0x7FFFull);
            unsigned pos = lo + i;
            float x = g_cx[cbase + slot];
            float y = g_cy[cbase + slot];
            float z = g_cz[cbase + slot];
            ob[(size_t)pos * 3 + 0] = x;
            ob[(size_t)pos * 3 + 1] = y;
            ob[(size_t)pos * 3 + 2] = z;
        }
    }

    // last block of each batch: warp 0 handles boundary-bin extras
    if (g == BG_BPB - 1) {
        __syncthreads();
        if (t < 32) {
            unsigned lane = (unsigned)t;
            int ec = g_extra_cnt[b]; if (ec > EX_CAP) ec = EX_CAP;
            for (int i = lane; i < EX_CAP; i += 32)
                sx[i] = (i < ec) ? g_extras[b * EX_CAP + i] : 0xFFFFFFFFFFFFFFFFull;
            __syncwarp();
            for (int k = 2; k <= EX_CAP; k <<= 1) {
                for (int j = k >> 1; j > 0; j >>= 1) {
                    unsigned i = ((lane & ~(unsigned)(j - 1)) << 1) | (lane & (unsigned)(j - 1));
                    unsigned ixj = i | (unsigned)j;
                    bool up = ((i & (unsigned)k) == 0);
                    unsigned long long a = sx[i], cc = sx[ixj];
                    if (up ? (a > cc) : (a < cc)) { sx[i] = cc; sx[ixj] = a; }
                    __syncwarp();
                }
            }
            unsigned base = g_base[b], need = g_need[b];
            for (unsigned i = lane; i < need && i < EX_CAP; i += 32) {
                unsigned slot = (unsigned)(sx[i] & 0x7FFFull);
                unsigned pos = base + i;
                float x = g_cx[cbase + slot];
                float y = g_cy[cbase + slot];
                float z = g_cz[cbase + slot];
                ob[(size_t)pos * 3 + 0] = x;
                ob[(size_t)pos * 3 + 1] = y;
                ob[(size_t)pos * 3 + 2] = z;
            }
            if (lane == 0) { g_extra_cnt[b] = 0; g_cand_cnt[b] = 0; }   // replay reset
        }
    }
}

// ---------------- launch ----------------
extern "C" void kernel_launch(void* const* d_in, const int* in_sizes, int n_in,
                              void* d_out, int out_size) {
    const float* p = (const float*)d_in[0];
    float* out = (float*)d_out;

    KeysParam kp;
    for (int b = 0; b < B_; b++) {
        unsigned kb0, kb1, s0, s1;
        tf2x32(0u, 42u, 0u, (unsigned)b, kb0, kb1);
        tf2x32(kb0, kb1, 0u, 0u, s0, s1);
        kp.k[2 * b]     = s0;
        kp.k[2 * b + 1] = s1;
    }

    k_main<<<(B_ * N_ / 4) / 256, 256>>>(p, kp);
    k_scan<<<B_, 1024>>>();
    k_scatter<<<B_ * SCAT_BPB, 256>>>();
    k_bingather<<<B_ * BG_BPB, 256>>>(out);
}

// round 12
// speedup vs baseline: 1.0630x; 1.0630x over previous
#include <cuda_runtime.h>

#define B_ 32
#define N_ 524288          // 2^19 points per batch
#define K_ 16384
#define T_RANK 425984u     // 3.25 * 2^17; E[cand] ~ 18.6k, 17 sigma above K
#define CAP 32768          // per-batch candidate capacity (15-bit slot)
#define FBINS 8192         // bins: bin = rank>>6 (only bins < 6656 used)
#define EX_CAP 64          // boundary-bin extras capacity (bin ~ Poisson(2.8))
#define BG_BPB 26          // bingather blocks per batch (26*256 = 6656 bins)
#define SEG_CAP 1280       // max keys per 256-bin segment (E~716, >20 sigma)

// key layout: [56:34]=rank(23)  [33:15]=idx(19)  [14:0]=slot(15)
// bin = key>>40 = rank>>6. Sorting by key == sorting by (rank, idx).

// ---------------- static device scratch (zero-init; kernels restore invariants) ----------------
__device__ int                g_cand_cnt[B_];
__device__ unsigned           g_hist[B_ * FBINS];      // built by k_main, zeroed by k_scansc
__device__ unsigned long long g_cand[B_ * CAP];        // unordered candidate keys
__device__ float4             g_cxyz[B_ * CAP];        // candidate coords (16 MB, L2-resident)
__device__ unsigned           g_binstart[B_ * FBINS];  // exclusive bin offsets
__device__ unsigned long long g_dst[B_ * K_];          // binned keys
__device__ unsigned long long g_extras[B_ * EX_CAP];
__device__ int                g_extra_cnt[B_];
__device__ unsigned           g_bstar[B_], g_base[B_], g_need[B_];

struct KeysParam { unsigned k[2 * B_]; };

// ---------------- threefry2x32, 20 rounds (exact JAX partitionable) ----------------
__host__ __device__ __forceinline__ unsigned rotl32(unsigned x, int r) {
#if defined(__CUDA_ARCH__)
    return __funnelshift_l(x, x, r);
#else
    return (x << r) | (x >> (32 - r));
#endif
}

__host__ __device__ __forceinline__ void tf2x32(unsigned k0, unsigned k1,
                                                unsigned x0, unsigned x1,
                                                unsigned& o0, unsigned& o1) {
    unsigned ks2 = k0 ^ k1 ^ 0x1BD11BDAu;
    x0 += k0; x1 += k1;
#define TF_ROUND(r) { x0 += x1; x1 = rotl32(x1, r); x1 ^= x0; }
    TF_ROUND(13) TF_ROUND(15) TF_ROUND(26) TF_ROUND(6)
    x0 += k1;  x1 += ks2 + 1u;
    TF_ROUND(17) TF_ROUND(29) TF_ROUND(16) TF_ROUND(24)
    x0 += ks2; x1 += k0 + 2u;
    TF_ROUND(13) TF_ROUND(15) TF_ROUND(26) TF_ROUND(6)
    x0 += k0;  x1 += k1 + 3u;
    TF_ROUND(17) TF_ROUND(29) TF_ROUND(16) TF_ROUND(24)
    x0 += k1;  x1 += ks2 + 4u;
    TF_ROUND(13) TF_ROUND(15) TF_ROUND(26) TF_ROUND(6)
    x0 += ks2; x1 += k0 + 5u;
#undef TF_ROUND
    o0 = x0; o1 = x1;
}

// ---------------- P1: validity + threefry + collect (keys + float4 coords) + histogram ----------------
__global__ void k_main(const float* __restrict__ p, KeysParam keys) {
    __shared__ int s_woff[8];
    __shared__ int s_base;

    unsigned t  = blockIdx.x * blockDim.x + threadIdx.x;   // one thread = 4 points
    unsigned e0 = t * 4u;
    unsigned b  = e0 >> 19;
    unsigned i0 = e0 & (N_ - 1);

    const float4* pv = reinterpret_cast<const float4*>(p) + (size_t)t * 3;
    float4 v0 = pv[0], v1 = pv[1], v2 = pv[2];
    float c[12] = { v0.x, v0.y, v0.z, v0.w, v1.x, v1.y,
                    v1.z, v1.w, v2.x, v2.y, v2.z, v2.w };

    unsigned k0 = keys.k[2 * b], k1 = keys.k[2 * b + 1];

    unsigned rank[4];
    bool cand[4];
#pragma unroll
    for (int j = 0; j < 4; j++) {
        float s = (c[3 * j] + c[3 * j + 1]) + c[3 * j + 2];   // XLA left-assoc sum
        unsigned a, d;
        tf2x32(k0, k1, 0u, i0 + (unsigned)j, a, d);           // counter (0, i)
        rank[j] = (a ^ d) >> 9;                               // 23-bit rank
        cand[j] = (s != 0.0f) && (rank[j] < T_RANK);
    }

    unsigned lane = threadIdx.x & 31u;
    unsigned wid  = threadIdx.x >> 5;
    unsigned lt_mask = (1u << lane) - 1u;
    unsigned msk[4];
    int tot = 0;
#pragma unroll
    for (int j = 0; j < 4; j++) {
        msk[j] = __ballot_sync(0xFFFFFFFFu, cand[j]);
        tot += __popc(msk[j]);
    }
    if (lane == 0) s_woff[wid] = tot;
    __syncthreads();
    if (threadIdx.x == 0) {
        int sum = 0;
#pragma unroll
        for (int w = 0; w < 8; w++) { int cc = s_woff[w]; s_woff[w] = sum; sum += cc; }
        s_base = atomicAdd(&g_cand_cnt[b], sum);
    }
    __syncthreads();
    int running = s_base + s_woff[wid];
#pragma unroll
    for (int j = 0; j < 4; j++) {
        if (cand[j]) {
            int pos = running + __popc(msk[j] & lt_mask);
            if (pos < CAP) {
                size_t sl = (size_t)b * CAP + pos;
                g_cand[sl] =
                    ((unsigned long long)rank[j] << 34) |
                    ((unsigned long long)(i0 + j) << 15) |
                    (unsigned long long)pos;
                g_cxyz[sl] = make_float4(c[3 * j], c[3 * j + 1], c[3 * j + 2], 0.0f);
            }
            atomicAdd(&g_hist[b * FBINS + (rank[j] >> 6)], 1u);   // RED, no return
        }
        running += __popc(msk[j]);
    }
}

// ---------------- P2: fused scan + scatter (block per batch; smem offset atomics) ----------------
__global__ void k_scansc() {
    __shared__ unsigned offs[FBINS];                     // 32 KB
    __shared__ unsigned s_wsum[32];
    __shared__ int s_ecnt;
    __shared__ unsigned s_bstar;

    int b = blockIdx.x, t = threadIdx.x;                 // 1024 threads
    unsigned lane = t & 31u, wid = t >> 5;
    unsigned* hist = &g_hist[b * FBINS];

    if (t == 0) s_ecnt = 0;
    {
        const uint4* hv = reinterpret_cast<const uint4*>(hist);
        uint4* ov = reinterpret_cast<uint4*>(offs);
        ov[t]        = hv[t];
        ov[t + 1024] = hv[t + 1024];
        // zero hist for next replay
        uint4 z = make_uint4(0, 0, 0, 0);
        uint4* hw = reinterpret_cast<uint4*>(hist);
        hw[t] = z; hw[t + 1024] = z;
    }
    __syncthreads();

    // scan over FBINS (8 bins/thread)
    unsigned loc[FBINS / 1024], run = 0;
#pragma unroll
    for (int r = 0; r < FBINS / 1024; r++) { loc[r] = run; run += offs[t * (FBINS / 1024) + r]; }
    unsigned wincl = run;
    for (int off = 1; off < 32; off <<= 1) {
        unsigned v = __shfl_up_sync(0xFFFFFFFFu, wincl, off);
        if (lane >= (unsigned)off) wincl += v;
    }
    if (lane == 31u) s_wsum[wid] = wincl;
    __syncthreads();
    if (wid == 0) {
        unsigned v = s_wsum[lane];
        unsigned sc = v;
        for (int off = 1; off < 32; off <<= 1) {
            unsigned u = __shfl_up_sync(0xFFFFFFFFu, sc, off);
            if (lane >= (unsigned)off) sc += u;
        }
        s_wsum[lane] = sc - v;
    }
    __syncthreads();
    unsigned incl = wincl + s_wsum[wid];
    unsigned excl = incl - run;

    if (excl < (unsigned)K_ && incl >= (unsigned)K_) {   // unique crossing thread
        unsigned cum = excl;
#pragma unroll
        for (int r = 0; r < FBINS / 1024; r++) {
            unsigned cc = offs[t * (FBINS / 1024) + r];
            if (cum + cc >= (unsigned)K_) {
                unsigned bst = (unsigned)(t * (FBINS / 1024) + r);
                s_bstar    = bst;
                g_bstar[b] = bst;
                g_base[b]  = cum;
                g_need[b]  = (unsigned)K_ - cum;
                break;
            }
            cum += cc;
        }
    }
    // offs -> global exclusive offsets (also publish binstart for bingather)
#pragma unroll
    for (int r = 0; r < FBINS / 1024; r++) {
        unsigned bin = (unsigned)t * (FBINS / 1024) + r;
        unsigned v = excl + loc[r];
        offs[bin] = v;
        g_binstart[b * FBINS + bin] = v;
    }
    __syncthreads();

    unsigned bstar = s_bstar;
    const unsigned long long* cand = &g_cand[(size_t)b * CAP];
    unsigned long long* dst = &g_dst[(size_t)b * K_];
    int C = g_cand_cnt[b]; if (C > CAP) C = CAP;

    // scatter with smem atomics
    for (int i = t; i < C; i += 1024) {
        unsigned long long key = cand[i];
        unsigned bin = (unsigned)(key >> 40);            // rank>>6
        if (bin < bstar) {
            unsigned pos = atomicAdd(&offs[bin], 1u);
            dst[pos] = key;
        } else if (bin == bstar) {
            int ep = atomicAdd(&s_ecnt, 1);
            if (ep < EX_CAP) g_extras[b * EX_CAP + ep] = key;
        }
    }
    __syncthreads();
    if (t == 0) {
        g_extra_cnt[b] = s_ecnt;
        g_cand_cnt[b]  = 0;                              // replay reset
    }
}

// ---------------- P3: segment-staged per-bin sort + L2-resident float4 gather ----------------
__global__ void k_bingather(float* __restrict__ out) {
    __shared__ unsigned long long seg[SEG_CAP];
    __shared__ unsigned long long sx[EX_CAP];

    int blk = blockIdx.x;
    int b   = blk / BG_BPB;
    int g   = blk % BG_BPB;
    int t   = threadIdx.x;                               // 256 threads
    unsigned bin0  = (unsigned)(g * 256);
    unsigned bstar = g_bstar[b];

    float* ob = out + (size_t)b * K_ * 3;
    const unsigned long long* dst = &g_dst[(size_t)b * K_];
    const unsigned* bs = &g_binstart[b * FBINS];
    const float4* cxyz = &g_cxyz[(size_t)b * CAP];

    unsigned binEnd = bin0 + 256u; if (binEnd > bstar) binEnd = bstar;
    if (bin0 < bstar) {
        unsigned lo  = bs[bin0];
        unsigned hi  = bs[binEnd];
        unsigned len = hi - lo; if (len > SEG_CAP) len = SEG_CAP;

        for (unsigned i = t; i < len; i += 256) seg[i] = dst[lo + i];
        __syncthreads();

        unsigned bin = bin0 + (unsigned)t;
        if (bin < binEnd) {
            unsigned s = bs[bin] - lo;
            unsigned e = bs[bin + 1] - lo;
            if (e > len) e = len;
            if (s > len) s = len;
            for (unsigned i = s + 1; i < e; i++) {
                unsigned long long v = seg[i];
                unsigned jj = i;
                while (jj > s && seg[jj - 1] > v) { seg[jj] = seg[jj - 1]; jj--; }
                seg[jj] = v;
            }
        }
        __syncthreads();

        // gather: one float4 L2 load per element
        for (unsigned i = t; i < len; i += 256) {
            unsigned slot = (unsigned)(seg[i] & 0x7FFFull);
            unsigned pos = lo + i;
            float4 v = cxyz[slot];
            ob[(size_t)pos * 3 + 0] = v.x;
            ob[(size_t)pos * 3 + 1] = v.y;
            ob[(size_t)pos * 3 + 2] = v.z;
        }
    }

    // last block of each batch: warp 0 handles boundary-bin extras
    if (g == BG_BPB - 1) {
        __syncthreads();
        if (t < 32) {
            unsigned lane = (unsigned)t;
            int ec = g_extra_cnt[b]; if (ec > EX_CAP) ec = EX_CAP;
            for (int i = lane; i < EX_CAP; i += 32)
                sx[i] = (i < ec) ? g_extras[b * EX_CAP + i] : 0xFFFFFFFFFFFFFFFFull;
            __syncwarp();
            for (int k = 2; k <= EX_CAP; k <<= 1) {
                for (int j = k >> 1; j > 0; j >>= 1) {
                    unsigned i = ((lane & ~(unsigned)(j - 1)) << 1) | (lane & (unsigned)(j - 1));
                    unsigned ixj = i | (unsigned)j;
                    bool up = ((i & (unsigned)k) == 0);
                    unsigned long long a = sx[i], cc = sx[ixj];
                    if (up ? (a > cc) : (a < cc)) { sx[i] = cc; sx[ixj] = a; }
                    __syncwarp();
                }
            }
            unsigned base = g_base[b], need = g_need[b];
            for (unsigned i = lane; i < need && i < EX_CAP; i += 32) {
                unsigned slot = (unsigned)(sx[i] & 0x7FFFull);
                unsigned pos = base + i;
                float4 v = cxyz[slot];
                ob[(size_t)pos * 3 + 0] = v.x;
                ob[(size_t)pos * 3 + 1] = v.y;
                ob[(size_t)pos * 3 + 2] = v.z;
            }
            if (lane == 0) g_extra_cnt[b] = 0;           // replay reset
        }
    }
}

// ---------------- launch ----------------
extern "C" void kernel_launch(void* const* d_in, const int* in_sizes, int n_in,
                              void* d_out, int out_size) {
    const float* p = (const float*)d_in[0];
    float* out = (float*)d_out;

    KeysParam kp;
    for (int b = 0; b < B_; b++) {
        unsigned kb0, kb1, s0, s1;
        tf2x32(0u, 42u, 0u, (unsigned)b, kb0, kb1);
        tf2x32(kb0, kb1, 0u, 0u, s0, s1);
        kp.k[2 * b]     = s0;
        kp.k[2 * b + 1] = s1;
    }

    k_main<<<(B_ * N_ / 4) / 256, 256>>>(p, kp);
    k_scansc<<<B_, 1024>>>();
    k_bingather<<<B_ * BG_BPB, 256>>>(out);
}